// round 2
// baseline (speedup 1.0000x reference)
#include <cuda_runtime.h>
#include <stdint.h>

#define N 8192
#define ROW_F4 (N / 4)              // 2048 float4 per row
#define TILE_F4 256                 // float4s per block (1024 columns)
#define TILES_X (ROW_F4 / TILE_F4)  // 8

// Packed cluster labels (N_CLUSTERS = 50 < 256, so uint8 is lossless)
__device__ uint8_t g_lab[N];

// Single-block prep: detect int32 vs int64 label storage, then pack to uint8.
// int64 little-endian labels < 2^32 have zero odd int32 words; int32 labels
// (random in [0,50)) have mostly nonzero odd words. Reads limited to the
// first 8192 int32 (32 KB) for detection, which is in-bounds for both dtypes.
__global__ void pack_labels_kernel(const int* __restrict__ raw) {
    __shared__ int s_any_odd_nonzero;
    const int tid = threadIdx.x;              // 1024 threads
    if (tid == 0) s_any_odd_nonzero = 0;
    __syncthreads();

    int local = 0;
    #pragma unroll
    for (int k = 0; k < 4; k++) {             // 4096 odd words
        int j = 2 * (tid + k * 1024) + 1;     // odd indices 1..8191
        if (raw[j] != 0) local = 1;
    }
    if (__syncthreads_or(local)) {
        // int32 labels: raw[i] is the label
        #pragma unroll
        for (int k = 0; k < 8; k++) {
            int i = tid + k * 1024;
            g_lab[i] = (uint8_t)raw[i];
        }
    } else {
        // int64 labels: low word at raw[2i]
        #pragma unroll
        for (int k = 0; k < 8; k++) {
            int i = tid + k * 1024;
            g_lab[i] = (uint8_t)raw[2 * i];
        }
    }
}

__device__ __forceinline__ float elem(float s, float d, bool same) {
    // gate at DTW_DELTA=5, sigma=1, epsilon=0.1
    // exp(-s^2)*exp(-d^2) = exp(-(s^2 + d^2))
    float e = __expf(-fmaf(s, s, d * d));
    e = same ? e : e * 0.1f;
    return (s < 5.0f) ? e : 0.0f;
}

__global__ void __launch_bounds__(TILE_F4)
dtw_mask_kernel(const float4* __restrict__ sd,
                const float4* __restrict__ dtw,
                float4* __restrict__ out) {
    __shared__ uchar4 slab[TILE_F4];   // 1024 column labels for this tile
    __shared__ uint8_t srow;

    const int row = blockIdx.y;
    const int tid = threadIdx.x;

    const uchar4* glab4 = reinterpret_cast<const uchar4*>(g_lab + blockIdx.x * (TILE_F4 * 4));
    slab[tid] = glab4[tid];
    if (tid == 0) srow = g_lab[row];
    __syncthreads();

    const long idx = (long)row * ROW_F4 + blockIdx.x * TILE_F4 + tid;
    float4 s = sd[idx];
    float4 d = dtw[idx];
    uchar4 lc = slab[tid];
    uint8_t lr = srow;

    float4 o;
    o.x = elem(s.x, d.x, lc.x == lr);
    o.y = elem(s.y, d.y, lc.y == lr);
    o.z = elem(s.z, d.z, lc.z == lr);
    o.w = elem(s.w, d.w, lc.w == lr);
    out[idx] = o;
}

extern "C" void kernel_launch(void* const* d_in, const int* in_sizes, int n_in,
                              void* d_out, int out_size) {
    // input order: adj_mx (unused), sd_mx, dtw_matrix, cluster_labels
    const float4* sd  = (const float4*)d_in[1];
    const float4* dtw = (const float4*)d_in[2];
    const int* labels_raw = (const int*)d_in[3];
    float4* out = (float4*)d_out;

    pack_labels_kernel<<<1, 1024>>>(labels_raw);

    dim3 grid(TILES_X, N);
    dtw_mask_kernel<<<grid, TILE_F4>>>(sd, dtw, out);
}